// round 11
// baseline (speedup 1.0000x reference)
#include <cuda_runtime.h>
#include <math.h>
#include <stdint.h>

#define B_SZ   1024
#define IN_DIM 2048
#define H_DIM  2048
#define KBLK   16
#define HB     128
#define G4H    8192   // 4*H

// ---------------- device scratch (no allocations allowed) ----------------
static __device__ float g_gates[B_SZ * G4H];       // 32 MB
static __device__ float g_s[B_SZ * HB];            // 512 KB (fp32 block sums)
static __device__ float g_t[B_SZ * 4 * HB];        // 2 MB (fp32 t = s @ Bm^T)
static __device__ float g_C32[4 * HB * HB];        // 256 KB (tf32-rounded A - Bm)
static __device__ float g_x32[B_SZ * IN_DIM];      // 8 MB
static __device__ float g_h32[B_SZ * H_DIM];       // 8 MB

// ---------------- helpers ----------------
__device__ __forceinline__ uint32_t smem_u32(const void* p) {
    uint32_t a;
    asm("{ .reg .u64 t; cvta.to.shared.u64 t, %1; cvt.u32.u64 %0, t; }" : "=r"(a) : "l"(p));
    return a;
}
__device__ __forceinline__ void cp16(uint32_t dst, const void* src) {
    asm volatile("cp.async.cg.shared.global [%0], [%1], 16;" :: "r"(dst), "l"(src));
}
#define CP_COMMIT() asm volatile("cp.async.commit_group;" ::: "memory")

__device__ __forceinline__ void mma8(float* c, const uint32_t* a, uint32_t b0, uint32_t b1) {
    asm volatile(
        "mma.sync.aligned.m16n8k8.row.col.f32.tf32.tf32.f32 "
        "{%0,%1,%2,%3}, {%4,%5,%6,%7}, {%8,%9}, {%0,%1,%2,%3};"
        : "+f"(c[0]), "+f"(c[1]), "+f"(c[2]), "+f"(c[3])
        : "r"(a[0]), "r"(a[1]), "r"(a[2]), "r"(a[3]), "r"(b0), "r"(b1));
}
__device__ __forceinline__ float tf32r(float x) {
    uint32_t u;
    asm("cvt.rna.tf32.f32 %0, %1;" : "=r"(u) : "f"(x));
    return __uint_as_float(u);
}

// ---------------- tf32 rounding pre-pass (x, h only) ----------------
__global__ void conv_tf32_kernel(const float* __restrict__ in, float* __restrict__ out) {
    int i = blockIdx.x * blockDim.x + threadIdx.x;
    float4 v = ((const float4*)in)[i];
    float4 o;
    o.x = tf32r(v.x); o.y = tf32r(v.y); o.z = tf32r(v.z); o.w = tf32r(v.w);
    ((float4*)out)[i] = o;
}

// s[b, j] = sum_kb h_prev[b, kb*128 + j]  (fp32)
__global__ void sum_blocks_kernel(const float* __restrict__ h_prev) {
    int b = blockIdx.x;
    int j = threadIdx.x;
    const float* hp = h_prev + (size_t)b * H_DIM + j;
    float acc = 0.f;
#pragma unroll
    for (int kb = 0; kb < KBLK; ++kb) acc += hp[kb * HB];
    g_s[b * HB + j] = acc;
}

// C32 = tf32(A - Bm)
__global__ void make_C_kernel(const float* __restrict__ A, const float* __restrict__ Bm) {
    int i = blockIdx.x * blockDim.x + threadIdx.x;
    float4 a = ((const float4*)A)[i];
    float4 b = ((const float4*)Bm)[i];
    float4 c;
    c.x = tf32r(a.x - b.x); c.y = tf32r(a.y - b.y);
    c.z = tf32r(a.z - b.z); c.w = tf32r(a.w - b.w);
    ((float4*)g_C32)[i] = c;
}

// ---------------- fused tensor GEMM (K = 2048 + 128) ----------------
// gates[m, n0+i] = sum_k x32[m,k] Win[n0+i,k] + sum_j h32[m, kb*128+j] C32[g][i][j]
// CTA tile 128x128, BK=32, 3-stage cp.async, 256 threads (8 warps: 4m x 2n,
// warp tile 32x64, ~127 regs). 2 CTAs/SM -> 16 warps/SM to hide LDS/barrier stalls.
#define BM 128
#define BN 128
#define BKT 32
#define AROW 36
#define ASTG (BM * AROW)          // 4608 floats
#define BSTG (BN * AROW)          // 4608 floats
#define NSTG 3
#define NIT  68                   // 64 main + 4 struct
#define GSMEM_BYTES (NSTG * (ASTG + BSTG) * 4)   // 110592

__global__ __launch_bounds__(256, 2)
void gemm_fused_kernel(const float* __restrict__ W) {
    extern __shared__ float sm[];
    float* sA = sm;                      // [NSTG][BM][AROW]
    float* sB = sm + NSTG * ASTG;        // [NSTG][BN][AROW]

    const int tid  = threadIdx.x;
    const int m0   = blockIdx.y * BM;
    const int n0   = blockIdx.x * BN;
    const int gI   = n0 >> 11;            // gate 0..3
    const int kb   = (n0 >> 7) & 15;      // block 0..15
    const int wid  = tid >> 5, lane = tid & 31;
    const int g    = lane >> 2, tg = lane & 3;
    const int wm   = wid & 3;             // 4 m-positions (32 rows each)
    const int wn   = wid >> 2;            // 2 n-positions (64 cols each)

    float acc[2][8][4];
#pragma unroll
    for (int mt = 0; mt < 2; ++mt)
#pragma unroll
        for (int nt = 0; nt < 8; ++nt)
#pragma unroll
            for (int q = 0; q < 4; ++q) acc[mt][nt][q] = 0.f;

    const uint32_t sAa = smem_u32(sA);
    const uint32_t sBa = smem_u32(sB);
    const int lrow = tid >> 3;            // 0..31
    const int lkc  = (tid & 7) * 4;       // {0,4,...,28}

    auto load = [&](int it) {
        const int s = it % NSTG;
        const float* ab; int alda;
        const float* bb; int blda;
        if (it < 64) {
            ab = g_x32 + (size_t)m0 * IN_DIM + it * BKT;   alda = IN_DIM;
            bb = W + (size_t)n0 * IN_DIM + it * BKT;       blda = IN_DIM;
        } else {
            ab = g_h32 + (size_t)m0 * H_DIM + kb * HB + (it - 64) * BKT;  alda = H_DIM;
            bb = g_C32 + gI * (HB * HB) + (it - 64) * BKT;                blda = HB;
        }
#pragma unroll
        for (int j = 0; j < 4; ++j) {      // A: 128 rows, 32 rows per pass
            int row = lrow + j * 32;
            cp16(sAa + (s * ASTG + row * AROW + lkc) * 4, ab + (size_t)row * alda + lkc);
        }
#pragma unroll
        for (int j = 0; j < 4; ++j) {      // B: 128 rows
            int row = lrow + j * 32;
            cp16(sBa + (s * BSTG + row * AROW + lkc) * 4, bb + (size_t)row * blda + lkc);
        }
        CP_COMMIT();
    };

    load(0); load(1);

    for (int it = 0; it < NIT; ++it) {
        if (it < NIT - 1) asm volatile("cp.async.wait_group 1;" ::: "memory");
        else              asm volatile("cp.async.wait_group 0;" ::: "memory");
        __syncthreads();
        if (it + 2 < NIT) load(it + 2);

        const float* A_s = sA + (it % NSTG) * ASTG;
        const float* B_s = sB + (it % NSTG) * BSTG;

#pragma unroll
        for (int ks = 0; ks < 4; ++ks) {
            const int k = ks * 8 + tg;
            uint32_t a[2][4];
#pragma unroll
            for (int mt = 0; mt < 2; ++mt) {
                const float* ap = A_s + (wm * 32 + mt * 16 + g) * AROW + k;
                a[mt][0] = __float_as_uint(ap[0]);
                a[mt][1] = __float_as_uint(ap[8 * AROW]);
                a[mt][2] = __float_as_uint(ap[4]);
                a[mt][3] = __float_as_uint(ap[8 * AROW + 4]);
            }
            uint32_t bf[8][2];
#pragma unroll
            for (int nt = 0; nt < 8; ++nt) {
                const float* bp = B_s + (wn * 64 + nt * 8 + g) * AROW + k;
                bf[nt][0] = __float_as_uint(bp[0]);
                bf[nt][1] = __float_as_uint(bp[4]);
            }
#pragma unroll
            for (int nt = 0; nt < 8; ++nt)
#pragma unroll
                for (int mt = 0; mt < 2; ++mt)
                    mma8(acc[mt][nt], a[mt], bf[nt][0], bf[nt][1]);
        }
    }

    // epilogue
#pragma unroll
    for (int mt = 0; mt < 2; ++mt) {
        const int r0 = m0 + wm * 32 + mt * 16 + g;
#pragma unroll
        for (int nt = 0; nt < 8; ++nt) {
            const int cc = n0 + wn * 64 + nt * 8 + 2 * tg;
            float2 v0 = make_float2(acc[mt][nt][0], acc[mt][nt][1]);
            float2 v1 = make_float2(acc[mt][nt][2], acc[mt][nt][3]);
            *(float2*)(g_gates + (size_t)r0 * G4H + cc) = v0;
            *(float2*)(g_gates + (size_t)(r0 + 8) * G4H + cc) = v1;
        }
    }
}

// ---------------- fp32 SIMT NT GEMM for t = s @ Bm^T ----------------
__global__ __launch_bounds__(256, 2)
void gemm_nt_kernel(const float* __restrict__ A, const float* __restrict__ B,
                    float* __restrict__ C,
                    int K, int lda, int ldb, int ldc) {
    __shared__ float As[16][128];
    __shared__ float Bs[16][128];

    const int m0 = blockIdx.y * 128;
    const int n0 = blockIdx.x * 128;
    const int tid = threadIdx.x;
    const int tx = tid & 15;
    const int ty = tid >> 4;

    float acc[8][8];
#pragma unroll
    for (int u = 0; u < 8; ++u)
#pragma unroll
        for (int v = 0; v < 8; ++v) acc[u][v] = 0.f;

    for (int k0 = 0; k0 < K; k0 += 16) {
#pragma unroll
        for (int l = 0; l < 2; ++l) {
            int f  = tid + l * 256;
            int r  = f >> 2;
            int c4 = (f & 3) * 4;
            float4 va = *(const float4*)(A + (size_t)(m0 + r) * lda + k0 + c4);
            As[c4 + 0][r] = va.x; As[c4 + 1][r] = va.y;
            As[c4 + 2][r] = va.z; As[c4 + 3][r] = va.w;
            float4 vb = *(const float4*)(B + (size_t)(n0 + r) * ldb + k0 + c4);
            Bs[c4 + 0][r] = vb.x; Bs[c4 + 1][r] = vb.y;
            Bs[c4 + 2][r] = vb.z; Bs[c4 + 3][r] = vb.w;
        }
        __syncthreads();
#pragma unroll
        for (int kk = 0; kk < 16; ++kk) {
            float a[8], b[8];
            *(float4*)&a[0] = *(const float4*)&As[kk][ty * 8];
            *(float4*)&a[4] = *(const float4*)&As[kk][ty * 8 + 4];
            *(float4*)&b[0] = *(const float4*)&Bs[kk][tx * 8];
            *(float4*)&b[4] = *(const float4*)&Bs[kk][tx * 8 + 4];
#pragma unroll
            for (int u = 0; u < 8; ++u)
#pragma unroll
                for (int v = 0; v < 8; ++v) acc[u][v] += a[u] * b[v];
        }
        __syncthreads();
    }

#pragma unroll
    for (int u = 0; u < 8; ++u) {
        float* crow = C + (size_t)(m0 + ty * 8 + u) * ldc + n0 + tx * 8;
#pragma unroll
        for (int v4 = 0; v4 < 2; ++v4) {
            float4 o;
            o.x = acc[u][v4 * 4 + 0]; o.y = acc[u][v4 * 4 + 1];
            o.z = acc[u][v4 * 4 + 2]; o.w = acc[u][v4 * 4 + 3];
            *(float4*)(crow + v4 * 4) = o;
        }
    }
}

// ---------------- elementwise LSTM epilogue (float4, adds fp32 t-term) ----------------
__global__ void lstm_elem_kernel(const float* __restrict__ c_prev, float* __restrict__ out) {
    int t = blockIdx.x * blockDim.x + threadIdx.x;   // 0 .. B*H/4-1
    int b = t >> 9;                     // 512 float4 per batch row
    int j = (t & 511) * 4;
    int jj = j & (HB - 1);
    const float* Gp = g_gates + (size_t)b * G4H + j;
    const float* tp = g_t + (size_t)b * (4 * HB) + jj;

    float4 gi = *(const float4*)(Gp);
    float4 gf = *(const float4*)(Gp + H_DIM);
    float4 gg = *(const float4*)(Gp + 2 * H_DIM);
    float4 go = *(const float4*)(Gp + 3 * H_DIM);
    float4 ti = *(const float4*)(tp);
    float4 tf = *(const float4*)(tp + HB);
    float4 tg_ = *(const float4*)(tp + 2 * HB);
    float4 to = *(const float4*)(tp + 3 * HB);
    float4 cp = *(const float4*)(c_prev + (size_t)b * H_DIM + j);

    float4 hv, cv;
    {
        float i_ = 1.f / (1.f + expf(-(gi.x + ti.x)));
        float f_ = 1.f / (1.f + expf(-(gf.x + tf.x)));
        float g_ = tanhf(gg.x + tg_.x);
        float o_ = 1.f / (1.f + expf(-(go.x + to.x)));
        cv.x = f_ * cp.x + i_ * g_;  hv.x = o_ * tanhf(cv.x);
    }
    {
        float i_ = 1.f / (1.f + expf(-(gi.y + ti.y)));
        float f_ = 1.f / (1.f + expf(-(gf.y + tf.y)));
        float g_ = tanhf(gg.y + tg_.y);
        float o_ = 1.f / (1.f + expf(-(go.y + to.y)));
        cv.y = f_ * cp.y + i_ * g_;  hv.y = o_ * tanhf(cv.y);
    }
    {
        float i_ = 1.f / (1.f + expf(-(gi.z + ti.z)));
        float f_ = 1.f / (1.f + expf(-(gf.z + tf.z)));
        float g_ = tanhf(gg.z + tg_.z);
        float o_ = 1.f / (1.f + expf(-(go.z + to.z)));
        cv.z = f_ * cp.z + i_ * g_;  hv.z = o_ * tanhf(cv.z);
    }
    {
        float i_ = 1.f / (1.f + expf(-(gi.w + ti.w)));
        float f_ = 1.f / (1.f + expf(-(gf.w + tf.w)));
        float g_ = tanhf(gg.w + tg_.w);
        float o_ = 1.f / (1.f + expf(-(go.w + to.w)));
        cv.w = f_ * cp.w + i_ * g_;  hv.w = o_ * tanhf(cv.w);
    }

    *(float4*)(out + (size_t)b * H_DIM + j) = hv;
    *(float4*)(out + (size_t)(B_SZ + b) * H_DIM + j) = cv;
}

// ---------------- launch ----------------
extern "C" void kernel_launch(void* const* d_in, const int* in_sizes, int n_in,
                              void* d_out, int out_size) {
    const float* x      = (const float*)d_in[0];
    const float* h_prev = (const float*)d_in[1];
    const float* c_prev = (const float*)d_in[2];
    const float* Win    = (const float*)d_in[3];
    const float* A      = (const float*)d_in[4];
    const float* Bm     = (const float*)d_in[5];
    float* out = (float*)d_out;

    void *p_x32, *p_h32, *p_s, *p_t;
    cudaGetSymbolAddress(&p_x32, g_x32);
    cudaGetSymbolAddress(&p_h32, g_h32);
    cudaGetSymbolAddress(&p_s, g_s);
    cudaGetSymbolAddress(&p_t, g_t);

    cudaFuncSetAttribute(gemm_fused_kernel, cudaFuncAttributeMaxDynamicSharedMemorySize,
                         GSMEM_BYTES);

    // ordered so the ncu capture slot (#4) lands on gemm_fused
    // 1-2) tf32-round x, h
    conv_tf32_kernel<<<(B_SZ * IN_DIM / 4) / 256, 256>>>(x, (float*)p_x32);
    conv_tf32_kernel<<<(B_SZ * H_DIM / 4) / 256, 256>>>(h_prev, (float*)p_h32);
    // 3) C32 = tf32(A - Bm)
    make_C_kernel<<<64, 256>>>(A, Bm);

    // 4) fused gates GEMM (main + struct) on tensor cores; W consumed raw
    {
        dim3 grid(G4H / BN, B_SZ / BM);
        gemm_fused_kernel<<<grid, 256, GSMEM_BYTES>>>(Win);
    }

    // 5) block sums (only feeds t / lstm)
    sum_blocks_kernel<<<B_SZ, HB>>>(h_prev);
    // 6) fp32 t = s @ Bm^T
    {
        dim3 grid(512 / 128, B_SZ / 128);
        gemm_nt_kernel<<<grid, 256>>>((const float*)p_s, Bm, (float*)p_t,
                                      HB, HB, HB, 4 * HB);
    }

    // 7) elementwise LSTM cell (+ t-term)
    lstm_elem_kernel<<<(B_SZ * H_DIM / 4) / 256, 256>>>(c_prev, out);
}

// round 12
// speedup vs baseline: 1.3861x; 1.3861x over previous
#include <cuda_runtime.h>
#include <cuda_fp16.h>
#include <math.h>
#include <stdint.h>

#define B_SZ   1024
#define IN_DIM 2048
#define H_DIM  2048
#define KBLK   16
#define HB     128
#define G4H    8192   // 4*H

// ---------------- device scratch (no allocations allowed) ----------------
static __device__ float  g_gates[B_SZ * G4H];        // 32 MB
static __device__ float  g_s[B_SZ * HB];             // fp32 block sums
static __device__ float  g_t[B_SZ * 4 * HB];         // fp32 t = s @ Bm^T
static __device__ __half g_C16[4 * HB * HB];         // fp16(A - Bm)
static __device__ __half g_xh[B_SZ * IN_DIM];        // 4 MB fp16 x
static __device__ __half g_hh[B_SZ * H_DIM];         // 4 MB fp16 h_prev
static __device__ __half g_wh[G4H * IN_DIM];         // 32 MB fp16 Win

// ---------------- helpers ----------------
__device__ __forceinline__ uint32_t smem_u32(const void* p) {
    uint32_t a;
    asm("{ .reg .u64 t; cvta.to.shared.u64 t, %1; cvt.u32.u64 %0, t; }" : "=r"(a) : "l"(p));
    return a;
}
__device__ __forceinline__ void cp16(uint32_t dst, const void* src) {
    asm volatile("cp.async.cg.shared.global [%0], [%1], 16;" :: "r"(dst), "l"(src));
}
#define CP_COMMIT() asm volatile("cp.async.commit_group;" ::: "memory")

__device__ __forceinline__ void mma16(float* c, const uint32_t* a, uint32_t b0, uint32_t b1) {
    asm volatile(
        "mma.sync.aligned.m16n8k16.row.col.f32.f16.f16.f32 "
        "{%0,%1,%2,%3}, {%4,%5,%6,%7}, {%8,%9}, {%0,%1,%2,%3};"
        : "+f"(c[0]), "+f"(c[1]), "+f"(c[2]), "+f"(c[3])
        : "r"(a[0]), "r"(a[1]), "r"(a[2]), "r"(a[3]), "r"(b0), "r"(b1));
}

// ---------------- fp16 conversion kernels ----------------
// one float4 -> 4 halves per thread
__global__ void conv_f16_kernel(const float* __restrict__ in, __half* __restrict__ out) {
    int i = blockIdx.x * blockDim.x + threadIdx.x;
    float4 v = ((const float4*)in)[i];
    __half2 h0 = __floats2half2_rn(v.x, v.y);
    __half2 h1 = __floats2half2_rn(v.z, v.w);
    ((__half2*)out)[2 * i]     = h0;
    ((__half2*)out)[2 * i + 1] = h1;
}

// x and h in one launch (same element count)
#define XH_QUADS (B_SZ * IN_DIM / 4)
__global__ void conv_xh_kernel(const float* __restrict__ x, const float* __restrict__ h) {
    int i = blockIdx.x * blockDim.x + threadIdx.x;
    const float* src; __half* dst; int idx;
    if (i < XH_QUADS) { src = x; dst = g_xh; idx = i; }
    else              { src = h; dst = g_hh; idx = i - XH_QUADS; }
    float4 v = ((const float4*)src)[idx];
    __half2 h0 = __floats2half2_rn(v.x, v.y);
    __half2 h1 = __floats2half2_rn(v.z, v.w);
    ((__half2*)dst)[2 * idx]     = h0;
    ((__half2*)dst)[2 * idx + 1] = h1;
}

// C16 = fp16(A - Bm)
__global__ void make_C_kernel(const float* __restrict__ A, const float* __restrict__ Bm) {
    int i = blockIdx.x * blockDim.x + threadIdx.x;
    float4 a = ((const float4*)A)[i];
    float4 b = ((const float4*)Bm)[i];
    __half2 c0 = __floats2half2_rn(a.x - b.x, a.y - b.y);
    __half2 c1 = __floats2half2_rn(a.z - b.z, a.w - b.w);
    ((__half2*)g_C16)[2 * i]     = c0;
    ((__half2*)g_C16)[2 * i + 1] = c1;
}

// s[b, j] = sum_kb h_prev[b, kb*128 + j]  (fp32)
__global__ void sum_blocks_kernel(const float* __restrict__ h_prev) {
    int b = blockIdx.x;
    int j = threadIdx.x;
    const float* hp = h_prev + (size_t)b * H_DIM + j;
    float acc = 0.f;
#pragma unroll
    for (int kb = 0; kb < KBLK; ++kb) acc += hp[kb * HB];
    g_s[b * HB + j] = acc;
}

// ---------------- fused fp16 tensor GEMM (K = 2048 + 128) ----------------
// gates[m, n0+i] = sum_k xh[m,k] wh[n0+i,k] + sum_j hh[m, kb*128+j] C16[g][i][j]
// CTA tile 128x128, BK=32, 4-stage cp.async, 256 threads (8 warps: 4m x 2n,
// warp 32x64). fp16 m16n8k16: half the HMMA instruction count of tf32 k8.
#define BM 128
#define BN 128
#define BKT 32
#define AROW_H 40                  // 32 + 8 pad halves (20 words -> conflict-free)
#define ASTG_H (BM * AROW_H)       // 5120 halves
#define BSTG_H (BN * AROW_H)
#define NSTG 4
#define NIT  68                    // 64 main + 4 struct
#define GSMEM_BYTES (NSTG * (ASTG_H + BSTG_H) * 2)   // 81920

__global__ __launch_bounds__(256, 2)
void gemm_fused_kernel(const __half* __restrict__ Wh) {
    extern __shared__ __half smh[];
    __half* sA = smh;                      // [NSTG][BM][AROW_H]
    __half* sB = smh + NSTG * ASTG_H;      // [NSTG][BN][AROW_H]

    const int tid  = threadIdx.x;
    const int m0   = blockIdx.y * BM;
    const int n0   = blockIdx.x * BN;
    const int gI   = n0 >> 11;            // gate 0..3
    const int kb   = (n0 >> 7) & 15;      // block 0..15
    const int wid  = tid >> 5, lane = tid & 31;
    const int g    = lane >> 2, tg = lane & 3;
    const int wm   = wid & 3;             // 4 m-positions (32 rows each)
    const int wn   = wid >> 2;            // 2 n-positions (64 cols each)

    float acc[2][8][4];
#pragma unroll
    for (int mt = 0; mt < 2; ++mt)
#pragma unroll
        for (int nt = 0; nt < 8; ++nt)
#pragma unroll
            for (int q = 0; q < 4; ++q) acc[mt][nt][q] = 0.f;

    const uint32_t sAa = smem_u32(sA);
    const uint32_t sBa = smem_u32(sB);
    // global->smem: 512 16B chunks per tile (128 rows x 4 chunks), 2/thread
    const int lrow = tid >> 2;            // 0..63
    const int lkc  = (tid & 3) * 8;       // half offset {0,8,16,24}

    auto load = [&](int it) {
        const int s = it & (NSTG - 1);
        const __half* ab; int alda;
        const __half* bb; int blda;
        if (it < 64) {
            ab = g_xh + (size_t)m0 * IN_DIM + it * BKT;   alda = IN_DIM;
            bb = Wh + (size_t)n0 * IN_DIM + it * BKT;     blda = IN_DIM;
        } else {
            ab = g_hh + (size_t)m0 * H_DIM + kb * HB + (it - 64) * BKT;  alda = H_DIM;
            bb = g_C16 + gI * (HB * HB) + (it - 64) * BKT;               blda = HB;
        }
#pragma unroll
        for (int j = 0; j < 2; ++j) {      // A: rows lrow, lrow+64
            int row = lrow + j * 64;
            cp16(sAa + (s * ASTG_H + row * AROW_H + lkc) * 2,
                 ab + (size_t)row * alda + lkc);
        }
#pragma unroll
        for (int j = 0; j < 2; ++j) {      // B
            int row = lrow + j * 64;
            cp16(sBa + (s * BSTG_H + row * AROW_H + lkc) * 2,
                 bb + (size_t)row * blda + lkc);
        }
        CP_COMMIT();
    };

    load(0); load(1); load(2);

    for (int it = 0; it < NIT; ++it) {
        if (it < NIT - 1) asm volatile("cp.async.wait_group 2;" ::: "memory");
        else              asm volatile("cp.async.wait_group 0;" ::: "memory");
        __syncthreads();
        if (it + 3 < NIT) load(it + 3);

        const __half* A_s = sA + (it & (NSTG - 1)) * ASTG_H;
        const __half* B_s = sB + (it & (NSTG - 1)) * BSTG_H;

#pragma unroll
        for (int ks = 0; ks < 2; ++ks) {          // 2 x k16 per BK=32
            const int k0h = ks * 16 + 2 * tg;
            uint32_t a[2][4];
#pragma unroll
            for (int mt = 0; mt < 2; ++mt) {
                const __half* ap = A_s + (wm * 32 + mt * 16 + g) * AROW_H + k0h;
                a[mt][0] = *(const uint32_t*)(ap);
                a[mt][1] = *(const uint32_t*)(ap + 8 * AROW_H);
                a[mt][2] = *(const uint32_t*)(ap + 8);
                a[mt][3] = *(const uint32_t*)(ap + 8 * AROW_H + 8);
            }
            uint32_t bf[8][2];
#pragma unroll
            for (int nt = 0; nt < 8; ++nt) {
                const __half* bp = B_s + (wn * 64 + nt * 8 + g) * AROW_H + k0h;
                bf[nt][0] = *(const uint32_t*)(bp);
                bf[nt][1] = *(const uint32_t*)(bp + 8);
            }
#pragma unroll
            for (int nt = 0; nt < 8; ++nt)
#pragma unroll
                for (int mt = 0; mt < 2; ++mt)
                    mma16(acc[mt][nt], a[mt], bf[nt][0], bf[nt][1]);
        }
    }

    // epilogue
#pragma unroll
    for (int mt = 0; mt < 2; ++mt) {
        const int r0 = m0 + wm * 32 + mt * 16 + g;
#pragma unroll
        for (int nt = 0; nt < 8; ++nt) {
            const int cc = n0 + wn * 64 + nt * 8 + 2 * tg;
            float2 v0 = make_float2(acc[mt][nt][0], acc[mt][nt][1]);
            float2 v1 = make_float2(acc[mt][nt][2], acc[mt][nt][3]);
            *(float2*)(g_gates + (size_t)r0 * G4H + cc) = v0;
            *(float2*)(g_gates + (size_t)(r0 + 8) * G4H + cc) = v1;
        }
    }
}

// ---------------- fp32 SIMT NT GEMM for t = s @ Bm^T ----------------
__global__ __launch_bounds__(256, 2)
void gemm_nt_kernel(const float* __restrict__ A, const float* __restrict__ B,
                    float* __restrict__ C,
                    int K, int lda, int ldb, int ldc) {
    __shared__ float As[16][128];
    __shared__ float Bs[16][128];

    const int m0 = blockIdx.y * 128;
    const int n0 = blockIdx.x * 128;
    const int tid = threadIdx.x;
    const int tx = tid & 15;
    const int ty = tid >> 4;

    float acc[8][8];
#pragma unroll
    for (int u = 0; u < 8; ++u)
#pragma unroll
        for (int v = 0; v < 8; ++v) acc[u][v] = 0.f;

    for (int k0 = 0; k0 < K; k0 += 16) {
#pragma unroll
        for (int l = 0; l < 2; ++l) {
            int f  = tid + l * 256;
            int r  = f >> 2;
            int c4 = (f & 3) * 4;
            float4 va = *(const float4*)(A + (size_t)(m0 + r) * lda + k0 + c4);
            As[c4 + 0][r] = va.x; As[c4 + 1][r] = va.y;
            As[c4 + 2][r] = va.z; As[c4 + 3][r] = va.w;
            float4 vb = *(const float4*)(B + (size_t)(n0 + r) * ldb + k0 + c4);
            Bs[c4 + 0][r] = vb.x; Bs[c4 + 1][r] = vb.y;
            Bs[c4 + 2][r] = vb.z; Bs[c4 + 3][r] = vb.w;
        }
        __syncthreads();
#pragma unroll
        for (int kk = 0; kk < 16; ++kk) {
            float a[8], b[8];
            *(float4*)&a[0] = *(const float4*)&As[kk][ty * 8];
            *(float4*)&a[4] = *(const float4*)&As[kk][ty * 8 + 4];
            *(float4*)&b[0] = *(const float4*)&Bs[kk][tx * 8];
            *(float4*)&b[4] = *(const float4*)&Bs[kk][tx * 8 + 4];
#pragma unroll
            for (int u = 0; u < 8; ++u)
#pragma unroll
                for (int v = 0; v < 8; ++v) acc[u][v] += a[u] * b[v];
        }
        __syncthreads();
    }

#pragma unroll
    for (int u = 0; u < 8; ++u) {
        float* crow = C + (size_t)(m0 + ty * 8 + u) * ldc + n0 + tx * 8;
#pragma unroll
        for (int v4 = 0; v4 < 2; ++v4) {
            float4 o;
            o.x = acc[u][v4 * 4 + 0]; o.y = acc[u][v4 * 4 + 1];
            o.z = acc[u][v4 * 4 + 2]; o.w = acc[u][v4 * 4 + 3];
            *(float4*)(crow + v4 * 4) = o;
        }
    }
}

// ---------------- elementwise LSTM epilogue (float4, adds fp32 t-term) ----------------
__global__ void lstm_elem_kernel(const float* __restrict__ c_prev, float* __restrict__ out) {
    int t = blockIdx.x * blockDim.x + threadIdx.x;   // 0 .. B*H/4-1
    int b = t >> 9;
    int j = (t & 511) * 4;
    int jj = j & (HB - 1);
    const float* Gp = g_gates + (size_t)b * G4H + j;
    const float* tp = g_t + (size_t)b * (4 * HB) + jj;

    float4 gi = *(const float4*)(Gp);
    float4 gf = *(const float4*)(Gp + H_DIM);
    float4 gg = *(const float4*)(Gp + 2 * H_DIM);
    float4 go = *(const float4*)(Gp + 3 * H_DIM);
    float4 ti = *(const float4*)(tp);
    float4 tf = *(const float4*)(tp + HB);
    float4 tg_ = *(const float4*)(tp + 2 * HB);
    float4 to = *(const float4*)(tp + 3 * HB);
    float4 cp = *(const float4*)(c_prev + (size_t)b * H_DIM + j);

    float4 hv, cv;
    {
        float i_ = 1.f / (1.f + expf(-(gi.x + ti.x)));
        float f_ = 1.f / (1.f + expf(-(gf.x + tf.x)));
        float g_ = tanhf(gg.x + tg_.x);
        float o_ = 1.f / (1.f + expf(-(go.x + to.x)));
        cv.x = f_ * cp.x + i_ * g_;  hv.x = o_ * tanhf(cv.x);
    }
    {
        float i_ = 1.f / (1.f + expf(-(gi.y + ti.y)));
        float f_ = 1.f / (1.f + expf(-(gf.y + tf.y)));
        float g_ = tanhf(gg.y + tg_.y);
        float o_ = 1.f / (1.f + expf(-(go.y + to.y)));
        cv.y = f_ * cp.y + i_ * g_;  hv.y = o_ * tanhf(cv.y);
    }
    {
        float i_ = 1.f / (1.f + expf(-(gi.z + ti.z)));
        float f_ = 1.f / (1.f + expf(-(gf.z + tf.z)));
        float g_ = tanhf(gg.z + tg_.z);
        float o_ = 1.f / (1.f + expf(-(go.z + to.z)));
        cv.z = f_ * cp.z + i_ * g_;  hv.z = o_ * tanhf(cv.z);
    }
    {
        float i_ = 1.f / (1.f + expf(-(gi.w + ti.w)));
        float f_ = 1.f / (1.f + expf(-(gf.w + tf.w)));
        float g_ = tanhf(gg.w + tg_.w);
        float o_ = 1.f / (1.f + expf(-(go.w + to.w)));
        cv.w = f_ * cp.w + i_ * g_;  hv.w = o_ * tanhf(cv.w);
    }

    *(float4*)(out + (size_t)b * H_DIM + j) = hv;
    *(float4*)(out + (size_t)(B_SZ + b) * H_DIM + j) = cv;
}

// ---------------- launch ----------------
extern "C" void kernel_launch(void* const* d_in, const int* in_sizes, int n_in,
                              void* d_out, int out_size) {
    const float* x      = (const float*)d_in[0];
    const float* h_prev = (const float*)d_in[1];
    const float* c_prev = (const float*)d_in[2];
    const float* Win    = (const float*)d_in[3];
    const float* A      = (const float*)d_in[4];
    const float* Bm     = (const float*)d_in[5];
    float* out = (float*)d_out;

    void *p_s, *p_t, *p_wh;
    cudaGetSymbolAddress(&p_s, g_s);
    cudaGetSymbolAddress(&p_t, g_t);
    cudaGetSymbolAddress(&p_wh, g_wh);

    cudaFuncSetAttribute(gemm_fused_kernel, cudaFuncAttributeMaxDynamicSharedMemorySize,
                         GSMEM_BYTES);

    // ordered so the ncu capture slot (#4) lands on gemm_fused
    // 1) W -> fp16
    conv_f16_kernel<<<(G4H * IN_DIM / 4) / 256, 256>>>(Win, (__half*)p_wh);
    // 2) x, h -> fp16 (single launch)
    conv_xh_kernel<<<(2 * XH_QUADS) / 256, 256>>>(x, h_prev);
    // 3) C16 = fp16(A - Bm)
    make_C_kernel<<<64, 256>>>(A, Bm);

    // 4) fused gates GEMM (main + struct), fp16 m16n8k16 tensor cores
    {
        dim3 grid(G4H / BN, B_SZ / BM);
        gemm_fused_kernel<<<grid, 256, GSMEM_BYTES>>>((const __half*)p_wh);
    }

    // 5) block sums (only feeds t / lstm)
    sum_blocks_kernel<<<B_SZ, HB>>>(h_prev);
    // 6) fp32 t = s @ Bm^T
    {
        dim3 grid(512 / 128, B_SZ / 128);
        gemm_nt_kernel<<<grid, 256>>>((const float*)p_s, Bm, (float*)p_t,
                                      HB, HB, HB, 4 * HB);
    }

    // 7) elementwise LSTM cell (+ t-term)
    lstm_elem_kernel<<<(B_SZ * H_DIM / 4) / 256, 256>>>(c_prev, out);
}

// round 15
// speedup vs baseline: 1.4898x; 1.0748x over previous
#include <cuda_runtime.h>
#include <cuda_fp16.h>
#include <math.h>
#include <stdint.h>

#define B_SZ   1024
#define IN_DIM 2048
#define H_DIM  2048
#define KBLK   16
#define HB     128
#define G4H    8192   // 4*H

// ---------------- device scratch (no allocations allowed) ----------------
static __device__ float  g_gates[B_SZ * G4H];        // 32 MB
static __device__ float  g_s[B_SZ * HB];             // fp32 block sums
static __device__ float  g_t[B_SZ * 4 * HB];         // fp32 t = s @ Bm^T
static __device__ __half g_C16[4 * HB * HB];         // fp16(A - Bm)
static __device__ __half g_xh[B_SZ * IN_DIM];        // 4 MB fp16 x
static __device__ __half g_hh[B_SZ * H_DIM];         // 4 MB fp16 h_prev
static __device__ __half g_wh[G4H * IN_DIM];         // 32 MB fp16 Win

// ---------------- helpers ----------------
__device__ __forceinline__ uint32_t smem_u32(const void* p) {
    uint32_t a;
    asm("{ .reg .u64 t; cvta.to.shared.u64 t, %1; cvt.u32.u64 %0, t; }" : "=r"(a) : "l"(p));
    return a;
}
__device__ __forceinline__ void cp16(uint32_t dst, const void* src) {
    asm volatile("cp.async.cg.shared.global [%0], [%1], 16;" :: "r"(dst), "l"(src));
}
#define CP_COMMIT() asm volatile("cp.async.commit_group;" ::: "memory")

__device__ __forceinline__ void mma16(float* c, const uint32_t* a, uint32_t b0, uint32_t b1) {
    asm volatile(
        "mma.sync.aligned.m16n8k16.row.col.f32.f16.f16.f32 "
        "{%0,%1,%2,%3}, {%4,%5,%6,%7}, {%8,%9}, {%0,%1,%2,%3};"
        : "+f"(c[0]), "+f"(c[1]), "+f"(c[2]), "+f"(c[3])
        : "r"(a[0]), "r"(a[1]), "r"(a[2]), "r"(a[3]), "r"(b0), "r"(b1));
}
__device__ __forceinline__ void ldsm4(uint32_t* r, uint32_t addr) {
    asm volatile("ldmatrix.sync.aligned.m8n8.x4.shared.b16 {%0,%1,%2,%3}, [%4];"
        : "=r"(r[0]), "=r"(r[1]), "=r"(r[2]), "=r"(r[3]) : "r"(addr));
}

// ---------------- fp16 conversion kernels ----------------
__global__ void conv_f16_kernel(const float* __restrict__ in, __half* __restrict__ out) {
    int i = blockIdx.x * blockDim.x + threadIdx.x;
    float4 v = ((const float4*)in)[i];
    ((__half2*)out)[2 * i]     = __floats2half2_rn(v.x, v.y);
    ((__half2*)out)[2 * i + 1] = __floats2half2_rn(v.z, v.w);
}

#define XH_QUADS (B_SZ * IN_DIM / 4)
__global__ void conv_xh_kernel(const float* __restrict__ x, const float* __restrict__ h) {
    int i = blockIdx.x * blockDim.x + threadIdx.x;
    const float* src; __half* dst; int idx;
    if (i < XH_QUADS) { src = x; dst = g_xh; idx = i; }
    else              { src = h; dst = g_hh; idx = i - XH_QUADS; }
    float4 v = ((const float4*)src)[idx];
    ((__half2*)dst)[2 * idx]     = __floats2half2_rn(v.x, v.y);
    ((__half2*)dst)[2 * idx + 1] = __floats2half2_rn(v.z, v.w);
}

__global__ void make_C_kernel(const float* __restrict__ A, const float* __restrict__ Bm) {
    int i = blockIdx.x * blockDim.x + threadIdx.x;
    float4 a = ((const float4*)A)[i];
    float4 b = ((const float4*)Bm)[i];
    ((__half2*)g_C16)[2 * i]     = __floats2half2_rn(a.x - b.x, a.y - b.y);
    ((__half2*)g_C16)[2 * i + 1] = __floats2half2_rn(a.z - b.z, a.w - b.w);
}

__global__ void sum_blocks_kernel(const float* __restrict__ h_prev) {
    int b = blockIdx.x;
    int j = threadIdx.x;
    const float* hp = h_prev + (size_t)b * H_DIM + j;
    float acc = 0.f;
#pragma unroll
    for (int kb = 0; kb < KBLK; ++kb) acc += hp[kb * HB];
    g_s[b * HB + j] = acc;
}

// ---------------- fused fp16 tensor GEMM (K = 2048 + 128) ----------------
// CTA 128x128, BK=32, 4-stage cp.async, 8 warps (4m x 2n, warp 32x64).
// Fragment loads via ldmatrix.x4: 12 LDSM/warp/iter instead of 48 LDS.
// wait_group 2 (NOT 3): with prefetch distance 3, groups it+1 and it+2 may be
// outstanding at iter it, but stage `it` must be complete before consumption.
#define BM 128
#define BN 128
#define BKT 32
#define AROW_H 40                  // 32 + 8 pad halves -> conflict-free ldmatrix
#define ASTG_H (BM * AROW_H)       // 5120 halves
#define BSTG_H (BN * AROW_H)
#define NSTG 4
#define NIT  68                    // 64 main + 4 struct
#define GSMEM_BYTES (NSTG * (ASTG_H + BSTG_H) * 2)   // 81920

__global__ __launch_bounds__(256, 2)
void gemm_fused_kernel(const __half* __restrict__ Wh) {
    extern __shared__ __half smh[];
    __half* sA = smh;                      // [NSTG][BM][AROW_H]
    __half* sB = smh + NSTG * ASTG_H;      // [NSTG][BN][AROW_H]

    const int tid  = threadIdx.x;
    const int m0   = blockIdx.y * BM;
    const int n0   = blockIdx.x * BN;
    const int gI   = n0 >> 11;            // gate 0..3
    const int kb   = (n0 >> 7) & 15;      // block 0..15
    const int wid  = tid >> 5, lane = tid & 31;
    const int g    = lane >> 2, tg = lane & 3;
    const int wm   = wid & 3;             // 4 m-positions (32 rows each)
    const int wn   = wid >> 2;            // 2 n-positions (64 cols each)

    float acc[2][8][4];
#pragma unroll
    for (int mt = 0; mt < 2; ++mt)
#pragma unroll
        for (int nt = 0; nt < 8; ++nt)
#pragma unroll
            for (int q = 0; q < 4; ++q) acc[mt][nt][q] = 0.f;

    const uint32_t sAa = smem_u32(sA);
    const uint32_t sBa = smem_u32(sB);

    // ldmatrix per-lane base addresses (in bytes)
    // A x4: lanes 0-15 -> rows m..m+15 @k0, lanes 16-31 -> same rows @k0+8
    const uint32_t aBase = sAa +
        (((wm * 32 + (lane & 15)) * AROW_H) + (lane >> 4) * 8) * 2;
    // B x4 (pair p): matrices {(2p,k0),(2p,k8),(2p+1,k0),(2p+1,k8)}
    const int bm   = lane >> 3;           // matrix 0..3
    const uint32_t bBase = sBa +
        (((wn * 64 + (bm >> 1) * 8 + (lane & 7)) * AROW_H) + (bm & 1) * 8) * 2;

    // global->smem: 128 rows x 4 chunks of 16B, 2 chunks/thread
    const int lrow = tid >> 2;            // 0..63
    const int lkc  = (tid & 3) * 8;       // half offset {0,8,16,24}

    auto load = [&](int it) {
        const int s = it & (NSTG - 1);
        const __half* ab; int alda;
        const __half* bb; int blda;
        if (it < 64) {
            ab = g_xh + (size_t)m0 * IN_DIM + it * BKT;   alda = IN_DIM;
            bb = Wh + (size_t)n0 * IN_DIM + it * BKT;     blda = IN_DIM;
        } else {
            ab = g_hh + (size_t)m0 * H_DIM + kb * HB + (it - 64) * BKT;  alda = H_DIM;
            bb = g_C16 + gI * (HB * HB) + (it - 64) * BKT;               blda = HB;
        }
#pragma unroll
        for (int j = 0; j < 2; ++j) {
            int row = lrow + j * 64;
            cp16(sAa + (s * ASTG_H + row * AROW_H + lkc) * 2,
                 ab + (size_t)row * alda + lkc);
        }
#pragma unroll
        for (int j = 0; j < 2; ++j) {
            int row = lrow + j * 64;
            cp16(sBa + (s * BSTG_H + row * AROW_H + lkc) * 2,
                 bb + (size_t)row * blda + lkc);
        }
        CP_COMMIT();
    };

    load(0); load(1); load(2);

    for (int it = 0; it < NIT; ++it) {
        if (it < NIT - 1) asm volatile("cp.async.wait_group 2;" ::: "memory");
        else              asm volatile("cp.async.wait_group 0;" ::: "memory");
        __syncthreads();
        if (it + 3 < NIT) load(it + 3);

        const int s = it & (NSTG - 1);
        const uint32_t aStg = aBase + s * ASTG_H * 2;
        const uint32_t bStg = bBase + s * BSTG_H * 2;

#pragma unroll
        for (int ks = 0; ks < 2; ++ks) {          // 2 x k16 per BK=32
            uint32_t a[2][4];
#pragma unroll
            for (int mt = 0; mt < 2; ++mt)
                ldsm4(a[mt], aStg + (mt * 16 * AROW_H + ks * 16) * 2);
            uint32_t bf[16];                      // [nt][2] flat
#pragma unroll
            for (int p = 0; p < 4; ++p)
                ldsm4(bf + 4 * p, bStg + (p * 16 * AROW_H + ks * 16) * 2);
#pragma unroll
            for (int nt = 0; nt < 8; ++nt)
#pragma unroll
                for (int mt = 0; mt < 2; ++mt)
                    mma16(acc[mt][nt], a[mt], bf[2 * nt], bf[2 * nt + 1]);
        }
    }

    // epilogue
#pragma unroll
    for (int mt = 0; mt < 2; ++mt) {
        const int r0 = m0 + wm * 32 + mt * 16 + g;
#pragma unroll
        for (int nt = 0; nt < 8; ++nt) {
            const int cc = n0 + wn * 64 + nt * 8 + 2 * tg;
            float2 v0 = make_float2(acc[mt][nt][0], acc[mt][nt][1]);
            float2 v1 = make_float2(acc[mt][nt][2], acc[mt][nt][3]);
            *(float2*)(g_gates + (size_t)r0 * G4H + cc) = v0;
            *(float2*)(g_gates + (size_t)(r0 + 8) * G4H + cc) = v1;
        }
    }
}

// ---------------- fp32 SIMT NT GEMM for t = s @ Bm^T ----------------
__global__ __launch_bounds__(256, 2)
void gemm_nt_kernel(const float* __restrict__ A, const float* __restrict__ B,
                    float* __restrict__ C,
                    int K, int lda, int ldb, int ldc) {
    __shared__ float As[16][128];
    __shared__ float Bs[16][128];

    const int m0 = blockIdx.y * 128;
    const int n0 = blockIdx.x * 128;
    const int tid = threadIdx.x;
    const int tx = tid & 15;
    const int ty = tid >> 4;

    float acc[8][8];
#pragma unroll
    for (int u = 0; u < 8; ++u)
#pragma unroll
        for (int v = 0; v < 8; ++v) acc[u][v] = 0.f;

    for (int k0 = 0; k0 < K; k0 += 16) {
#pragma unroll
        for (int l = 0; l < 2; ++l) {
            int f  = tid + l * 256;
            int r  = f >> 2;
            int c4 = (f & 3) * 4;
            float4 va = *(const float4*)(A + (size_t)(m0 + r) * lda + k0 + c4);
            As[c4 + 0][r] = va.x; As[c4 + 1][r] = va.y;
            As[c4 + 2][r] = va.z; As[c4 + 3][r] = va.w;
            float4 vb = *(const float4*)(B + (size_t)(n0 + r) * ldb + k0 + c4);
            Bs[c4 + 0][r] = vb.x; Bs[c4 + 1][r] = vb.y;
            Bs[c4 + 2][r] = vb.z; Bs[c4 + 3][r] = vb.w;
        }
        __syncthreads();
#pragma unroll
        for (int kk = 0; kk < 16; ++kk) {
            float a[8], b[8];
            *(float4*)&a[0] = *(const float4*)&As[kk][ty * 8];
            *(float4*)&a[4] = *(const float4*)&As[kk][ty * 8 + 4];
            *(float4*)&b[0] = *(const float4*)&Bs[kk][tx * 8];
            *(float4*)&b[4] = *(const float4*)&Bs[kk][tx * 8 + 4];
#pragma unroll
            for (int u = 0; u < 8; ++u)
#pragma unroll
                for (int v = 0; v < 8; ++v) acc[u][v] += a[u] * b[v];
        }
        __syncthreads();
    }

#pragma unroll
    for (int u = 0; u < 8; ++u) {
        float* crow = C + (size_t)(m0 + ty * 8 + u) * ldc + n0 + tx * 8;
#pragma unroll
        for (int v4 = 0; v4 < 2; ++v4) {
            float4 o;
            o.x = acc[u][v4 * 4 + 0]; o.y = acc[u][v4 * 4 + 1];
            o.z = acc[u][v4 * 4 + 2]; o.w = acc[u][v4 * 4 + 3];
            *(float4*)(crow + v4 * 4) = o;
        }
    }
}

// ---------------- elementwise LSTM epilogue (float4, adds fp32 t-term) ----------------
__global__ void lstm_elem_kernel(const float* __restrict__ c_prev, float* __restrict__ out) {
    int t = blockIdx.x * blockDim.x + threadIdx.x;
    int b = t >> 9;
    int j = (t & 511) * 4;
    int jj = j & (HB - 1);
    const float* Gp = g_gates + (size_t)b * G4H + j;
    const float* tp = g_t + (size_t)b * (4 * HB) + jj;

    float4 gi = *(const float4*)(Gp);
    float4 gf = *(const float4*)(Gp + H_DIM);
    float4 gg = *(const float4*)(Gp + 2 * H_DIM);
    float4 go = *(const float4*)(Gp + 3 * H_DIM);
    float4 ti = *(const float4*)(tp);
    float4 tf = *(const float4*)(tp + HB);
    float4 tg_ = *(const float4*)(tp + 2 * HB);
    float4 to = *(const float4*)(tp + 3 * HB);
    float4 cp = *(const float4*)(c_prev + (size_t)b * H_DIM + j);

    float4 hv, cv;
    {
        float i_ = 1.f / (1.f + expf(-(gi.x + ti.x)));
        float f_ = 1.f / (1.f + expf(-(gf.x + tf.x)));
        float g_ = tanhf(gg.x + tg_.x);
        float o_ = 1.f / (1.f + expf(-(go.x + to.x)));
        cv.x = f_ * cp.x + i_ * g_;  hv.x = o_ * tanhf(cv.x);
    }
    {
        float i_ = 1.f / (1.f + expf(-(gi.y + ti.y)));
        float f_ = 1.f / (1.f + expf(-(gf.y + tf.y)));
        float g_ = tanhf(gg.y + tg_.y);
        float o_ = 1.f / (1.f + expf(-(go.y + to.y)));
        cv.y = f_ * cp.y + i_ * g_;  hv.y = o_ * tanhf(cv.y);
    }
    {
        float i_ = 1.f / (1.f + expf(-(gi.z + ti.z)));
        float f_ = 1.f / (1.f + expf(-(gf.z + tf.z)));
        float g_ = tanhf(gg.z + tg_.z);
        float o_ = 1.f / (1.f + expf(-(go.z + to.z)));
        cv.z = f_ * cp.z + i_ * g_;  hv.z = o_ * tanhf(cv.z);
    }
    {
        float i_ = 1.f / (1.f + expf(-(gi.w + ti.w)));
        float f_ = 1.f / (1.f + expf(-(gf.w + tf.w)));
        float g_ = tanhf(gg.w + tg_.w);
        float o_ = 1.f / (1.f + expf(-(go.w + to.w)));
        cv.w = f_ * cp.w + i_ * g_;  hv.w = o_ * tanhf(cv.w);
    }

    *(float4*)(out + (size_t)b * H_DIM + j) = hv;
    *(float4*)(out + (size_t)(B_SZ + b) * H_DIM + j) = cv;
}

// ---------------- launch ----------------
extern "C" void kernel_launch(void* const* d_in, const int* in_sizes, int n_in,
                              void* d_out, int out_size) {
    const float* x      = (const float*)d_in[0];
    const float* h_prev = (const float*)d_in[1];
    const float* c_prev = (const float*)d_in[2];
    const float* Win    = (const float*)d_in[3];
    const float* A      = (const float*)d_in[4];
    const float* Bm     = (const float*)d_in[5];
    float* out = (float*)d_out;

    void *p_s, *p_t, *p_wh;
    cudaGetSymbolAddress(&p_s, g_s);
    cudaGetSymbolAddress(&p_t, g_t);
    cudaGetSymbolAddress(&p_wh, g_wh);

    cudaFuncSetAttribute(gemm_fused_kernel, cudaFuncAttributeMaxDynamicSharedMemorySize,
                         GSMEM_BYTES);

    // ordered so the ncu capture slot (#4) lands on gemm_fused
    // 1) W -> fp16
    conv_f16_kernel<<<(G4H * IN_DIM / 4) / 256, 256>>>(Win, (__half*)p_wh);
    // 2) x, h -> fp16 (single launch)
    conv_xh_kernel<<<(2 * XH_QUADS) / 256, 256>>>(x, h_prev);
    // 3) C16 = fp16(A - Bm)
    make_C_kernel<<<64, 256>>>(A, Bm);

    // 4) fused gates GEMM (main + struct), fp16 m16n8k16 + ldmatrix
    {
        dim3 grid(G4H / BN, B_SZ / BM);
        gemm_fused_kernel<<<grid, 256, GSMEM_BYTES>>>((const __half*)p_wh);
    }

    // 5) block sums (only feeds t / lstm)
    sum_blocks_kernel<<<B_SZ, HB>>>(h_prev);
    // 6) fp32 t = s @ Bm^T
    {
        dim3 grid(512 / 128, B_SZ / 128);
        gemm_nt_kernel<<<grid, 256>>>((const float*)p_s, Bm, (float*)p_t,
                                      HB, HB, HB, 4 * HB);
    }

    // 7) elementwise LSTM cell (+ t-term)
    lstm_elem_kernel<<<(B_SZ * H_DIM / 4) / 256, 256>>>(c_prev, out);
}

// round 16
// speedup vs baseline: 1.6460x; 1.1048x over previous
#include <cuda_runtime.h>
#include <cuda_fp16.h>
#include <math.h>
#include <stdint.h>

#define B_SZ   1024
#define IN_DIM 2048
#define H_DIM  2048
#define KBLK   16
#define HB     128
#define G4H    8192   // 4*H

// ---------------- device scratch (no allocations allowed) ----------------
static __device__ float  g_gates[B_SZ * G4H];        // 32 MB
static __device__ float  g_s[B_SZ * HB];             // fp32 block sums
static __device__ float  g_t[B_SZ * 4 * HB];         // fp32 t = s @ Bm^T
static __device__ __half g_C16[4 * HB * HB];         // fp16(A - Bm)
static __device__ __half g_xh[B_SZ * IN_DIM];        // 4 MB fp16 x
static __device__ __half g_hh[B_SZ * H_DIM];         // 4 MB fp16 h_prev
static __device__ __half g_wh[G4H * IN_DIM];         // 32 MB fp16 Win

// ---------------- helpers ----------------
__device__ __forceinline__ uint32_t smem_u32(const void* p) {
    uint32_t a;
    asm("{ .reg .u64 t; cvta.to.shared.u64 t, %1; cvt.u32.u64 %0, t; }" : "=r"(a) : "l"(p));
    return a;
}
__device__ __forceinline__ void cp16(uint32_t dst, const void* src) {
    asm volatile("cp.async.cg.shared.global [%0], [%1], 16;" :: "r"(dst), "l"(src));
}
#define CP_COMMIT() asm volatile("cp.async.commit_group;" ::: "memory")

__device__ __forceinline__ void mma16(float* c, const uint32_t* a, uint32_t b0, uint32_t b1) {
    asm volatile(
        "mma.sync.aligned.m16n8k16.row.col.f32.f16.f16.f32 "
        "{%0,%1,%2,%3}, {%4,%5,%6,%7}, {%8,%9}, {%0,%1,%2,%3};"
        : "+f"(c[0]), "+f"(c[1]), "+f"(c[2]), "+f"(c[3])
        : "r"(a[0]), "r"(a[1]), "r"(a[2]), "r"(a[3]), "r"(b0), "r"(b1));
}
__device__ __forceinline__ void ldsm4(uint32_t* r, uint32_t addr) {
    asm volatile("ldmatrix.sync.aligned.m8n8.x4.shared.b16 {%0,%1,%2,%3}, [%4];"
        : "=r"(r[0]), "=r"(r[1]), "=r"(r[2]), "=r"(r[3]) : "r"(addr));
}

// ---------------- fp16 conversion kernels ----------------
__global__ void conv_f16_kernel(const float* __restrict__ in, __half* __restrict__ out) {
    int i = blockIdx.x * blockDim.x + threadIdx.x;
    float4 v = ((const float4*)in)[i];
    ((__half2*)out)[2 * i]     = __floats2half2_rn(v.x, v.y);
    ((__half2*)out)[2 * i + 1] = __floats2half2_rn(v.z, v.w);
}

#define XH_QUADS (B_SZ * IN_DIM / 4)
__global__ void conv_xh_kernel(const float* __restrict__ x, const float* __restrict__ h) {
    int i = blockIdx.x * blockDim.x + threadIdx.x;
    const float* src; __half* dst; int idx;
    if (i < XH_QUADS) { src = x; dst = g_xh; idx = i; }
    else              { src = h; dst = g_hh; idx = i - XH_QUADS; }
    float4 v = ((const float4*)src)[idx];
    ((__half2*)dst)[2 * idx]     = __floats2half2_rn(v.x, v.y);
    ((__half2*)dst)[2 * idx + 1] = __floats2half2_rn(v.z, v.w);
}

__global__ void make_C_kernel(const float* __restrict__ A, const float* __restrict__ Bm) {
    int i = blockIdx.x * blockDim.x + threadIdx.x;
    float4 a = ((const float4*)A)[i];
    float4 b = ((const float4*)Bm)[i];
    ((__half2*)g_C16)[2 * i]     = __floats2half2_rn(a.x - b.x, a.y - b.y);
    ((__half2*)g_C16)[2 * i + 1] = __floats2half2_rn(a.z - b.z, a.w - b.w);
}

__global__ void sum_blocks_kernel(const float* __restrict__ h_prev) {
    int b = blockIdx.x;
    int j = threadIdx.x;
    const float* hp = h_prev + (size_t)b * H_DIM + j;
    float acc = 0.f;
#pragma unroll
    for (int kb = 0; kb < KBLK; ++kb) acc += hp[kb * HB];
    g_s[b * HB + j] = acc;
}

// ---------------- fused fp16 tensor GEMM (K = 2048 + 128) ----------------
// CTA 128x128, BK=64, 3-stage cp.async, 8 warps (4m x 2n, warp 32x64).
// BK=64 halves the per-iteration barrier count (34 iters vs 68).
#define BM 128
#define BN 128
#define BKT 64
#define AROW_H 72                  // 64 + 8 pad halves -> conflict-free ldmatrix
#define ASTG_H (BM * AROW_H)       // 9216 halves
#define BSTG_H (BN * AROW_H)
#define NSTG 3
#define NIT  34                    // 32 main + 2 struct
#define GSMEM_BYTES (NSTG * (ASTG_H + BSTG_H) * 2)   // 110592

__global__ __launch_bounds__(256, 2)
void gemm_fused_kernel(const __half* __restrict__ Wh) {
    extern __shared__ __half smh[];
    __half* sA = smh;                      // [NSTG][BM][AROW_H]
    __half* sB = smh + NSTG * ASTG_H;      // [NSTG][BN][AROW_H]

    const int tid  = threadIdx.x;
    const int m0   = blockIdx.y * BM;
    const int n0   = blockIdx.x * BN;
    const int gI   = n0 >> 11;            // gate 0..3
    const int kb   = (n0 >> 7) & 15;      // block 0..15
    const int wid  = tid >> 5, lane = tid & 31;
    const int g    = lane >> 2, tg = lane & 3;
    const int wm   = wid & 3;             // 4 m-positions (32 rows each)
    const int wn   = wid >> 2;            // 2 n-positions (64 cols each)

    float acc[2][8][4];
#pragma unroll
    for (int mt = 0; mt < 2; ++mt)
#pragma unroll
        for (int nt = 0; nt < 8; ++nt)
#pragma unroll
            for (int q = 0; q < 4; ++q) acc[mt][nt][q] = 0.f;

    const uint32_t sAa = smem_u32(sA);
    const uint32_t sBa = smem_u32(sB);

    // ldmatrix per-lane base addresses (in bytes)
    const uint32_t aBase = sAa +
        (((wm * 32 + (lane & 15)) * AROW_H) + (lane >> 4) * 8) * 2;
    const int bm   = lane >> 3;           // matrix 0..3
    const uint32_t bBase = sBa +
        (((wn * 64 + (bm >> 1) * 8 + (lane & 7)) * AROW_H) + (bm & 1) * 8) * 2;

    // global->smem: 128 rows x 8 chunks of 16B = 1024 chunks, 4/thread
    const int lrow = tid >> 3;            // 0..31
    const int lkc  = (tid & 7) * 8;       // half offset {0,8,...,56}

    auto load = [&](int it) {
        const int s = it % NSTG;
        const __half* ab; int alda;
        const __half* bb; int blda;
        if (it < 32) {
            ab = g_xh + (size_t)m0 * IN_DIM + it * BKT;   alda = IN_DIM;
            bb = Wh + (size_t)n0 * IN_DIM + it * BKT;     blda = IN_DIM;
        } else {
            ab = g_hh + (size_t)m0 * H_DIM + kb * HB + (it - 32) * BKT;  alda = H_DIM;
            bb = g_C16 + gI * (HB * HB) + (it - 32) * BKT;               blda = HB;
        }
#pragma unroll
        for (int j = 0; j < 4; ++j) {
            int row = lrow + j * 32;
            cp16(sAa + (s * ASTG_H + row * AROW_H + lkc) * 2,
                 ab + (size_t)row * alda + lkc);
        }
#pragma unroll
        for (int j = 0; j < 4; ++j) {
            int row = lrow + j * 32;
            cp16(sBa + (s * BSTG_H + row * AROW_H + lkc) * 2,
                 bb + (size_t)row * blda + lkc);
        }
        CP_COMMIT();
    };

    load(0); load(1);

    for (int it = 0; it < NIT; ++it) {
        if (it < NIT - 1) asm volatile("cp.async.wait_group 1;" ::: "memory");
        else              asm volatile("cp.async.wait_group 0;" ::: "memory");
        __syncthreads();
        if (it + 2 < NIT) load(it + 2);

        const int s = it % NSTG;
        const uint32_t aStg = aBase + s * ASTG_H * 2;
        const uint32_t bStg = bBase + s * BSTG_H * 2;

#pragma unroll
        for (int ks = 0; ks < 4; ++ks) {          // 4 x k16 per BK=64
            uint32_t a[2][4];
#pragma unroll
            for (int mt = 0; mt < 2; ++mt)
                ldsm4(a[mt], aStg + (mt * 16 * AROW_H + ks * 16) * 2);
            uint32_t bf[16];
#pragma unroll
            for (int p = 0; p < 4; ++p)
                ldsm4(bf + 4 * p, bStg + (p * 16 * AROW_H + ks * 16) * 2);
#pragma unroll
            for (int nt = 0; nt < 8; ++nt)
#pragma unroll
                for (int mt = 0; mt < 2; ++mt)
                    mma16(acc[mt][nt], a[mt], bf[2 * nt], bf[2 * nt + 1]);
        }
    }

    // epilogue
#pragma unroll
    for (int mt = 0; mt < 2; ++mt) {
        const int r0 = m0 + wm * 32 + mt * 16 + g;
#pragma unroll
        for (int nt = 0; nt < 8; ++nt) {
            const int cc = n0 + wn * 64 + nt * 8 + 2 * tg;
            float2 v0 = make_float2(acc[mt][nt][0], acc[mt][nt][1]);
            float2 v1 = make_float2(acc[mt][nt][2], acc[mt][nt][3]);
            *(float2*)(g_gates + (size_t)r0 * G4H + cc) = v0;
            *(float2*)(g_gates + (size_t)(r0 + 8) * G4H + cc) = v1;
        }
    }
}

// ---------------- fp32 SIMT NT GEMM for t = s @ Bm^T ----------------
__global__ __launch_bounds__(256, 2)
void gemm_nt_kernel(const float* __restrict__ A, const float* __restrict__ B,
                    float* __restrict__ C,
                    int K, int lda, int ldb, int ldc) {
    __shared__ float As[16][128];
    __shared__ float Bs[16][128];

    const int m0 = blockIdx.y * 128;
    const int n0 = blockIdx.x * 128;
    const int tid = threadIdx.x;
    const int tx = tid & 15;
    const int ty = tid >> 4;

    float acc[8][8];
#pragma unroll
    for (int u = 0; u < 8; ++u)
#pragma unroll
        for (int v = 0; v < 8; ++v) acc[u][v] = 0.f;

    for (int k0 = 0; k0 < K; k0 += 16) {
#pragma unroll
        for (int l = 0; l < 2; ++l) {
            int f  = tid + l * 256;
            int r  = f >> 2;
            int c4 = (f & 3) * 4;
            float4 va = *(const float4*)(A + (size_t)(m0 + r) * lda + k0 + c4);
            As[c4 + 0][r] = va.x; As[c4 + 1][r] = va.y;
            As[c4 + 2][r] = va.z; As[c4 + 3][r] = va.w;
            float4 vb = *(const float4*)(B + (size_t)(n0 + r) * ldb + k0 + c4);
            Bs[c4 + 0][r] = vb.x; Bs[c4 + 1][r] = vb.y;
            Bs[c4 + 2][r] = vb.z; Bs[c4 + 3][r] = vb.w;
        }
        __syncthreads();
#pragma unroll
        for (int kk = 0; kk < 16; ++kk) {
            float a[8], b[8];
            *(float4*)&a[0] = *(const float4*)&As[kk][ty * 8];
            *(float4*)&a[4] = *(const float4*)&As[kk][ty * 8 + 4];
            *(float4*)&b[0] = *(const float4*)&Bs[kk][tx * 8];
            *(float4*)&b[4] = *(const float4*)&Bs[kk][tx * 8 + 4];
#pragma unroll
            for (int u = 0; u < 8; ++u)
#pragma unroll
                for (int v = 0; v < 8; ++v) acc[u][v] += a[u] * b[v];
        }
        __syncthreads();
    }

#pragma unroll
    for (int u = 0; u < 8; ++u) {
        float* crow = C + (size_t)(m0 + ty * 8 + u) * ldc + n0 + tx * 8;
#pragma unroll
        for (int v4 = 0; v4 < 2; ++v4) {
            float4 o;
            o.x = acc[u][v4 * 4 + 0]; o.y = acc[u][v4 * 4 + 1];
            o.z = acc[u][v4 * 4 + 2]; o.w = acc[u][v4 * 4 + 3];
            *(float4*)(crow + v4 * 4) = o;
        }
    }
}

// ---------------- elementwise LSTM epilogue (float4, adds fp32 t-term) ----------------
__global__ void lstm_elem_kernel(const float* __restrict__ c_prev, float* __restrict__ out) {
    int t = blockIdx.x * blockDim.x + threadIdx.x;
    int b = t >> 9;
    int j = (t & 511) * 4;
    int jj = j & (HB - 1);
    const float* Gp = g_gates + (size_t)b * G4H + j;
    const float* tp = g_t + (size_t)b * (4 * HB) + jj;

    float4 gi = *(const float4*)(Gp);
    float4 gf = *(const float4*)(Gp + H_DIM);
    float4 gg = *(const float4*)(Gp + 2 * H_DIM);
    float4 go = *(const float4*)(Gp + 3 * H_DIM);
    float4 ti = *(const float4*)(tp);
    float4 tf = *(const float4*)(tp + HB);
    float4 tg_ = *(const float4*)(tp + 2 * HB);
    float4 to = *(const float4*)(tp + 3 * HB);
    float4 cp = *(const float4*)(c_prev + (size_t)b * H_DIM + j);

    float4 hv, cv;
    {
        float i_ = 1.f / (1.f + expf(-(gi.x + ti.x)));
        float f_ = 1.f / (1.f + expf(-(gf.x + tf.x)));
        float g_ = tanhf(gg.x + tg_.x);
        float o_ = 1.f / (1.f + expf(-(go.x + to.x)));
        cv.x = f_ * cp.x + i_ * g_;  hv.x = o_ * tanhf(cv.x);
    }
    {
        float i_ = 1.f / (1.f + expf(-(gi.y + ti.y)));
        float f_ = 1.f / (1.f + expf(-(gf.y + tf.y)));
        float g_ = tanhf(gg.y + tg_.y);
        float o_ = 1.f / (1.f + expf(-(go.y + to.y)));
        cv.y = f_ * cp.y + i_ * g_;  hv.y = o_ * tanhf(cv.y);
    }
    {
        float i_ = 1.f / (1.f + expf(-(gi.z + ti.z)));
        float f_ = 1.f / (1.f + expf(-(gf.z + tf.z)));
        float g_ = tanhf(gg.z + tg_.z);
        float o_ = 1.f / (1.f + expf(-(go.z + to.z)));
        cv.z = f_ * cp.z + i_ * g_;  hv.z = o_ * tanhf(cv.z);
    }
    {
        float i_ = 1.f / (1.f + expf(-(gi.w + ti.w)));
        float f_ = 1.f / (1.f + expf(-(gf.w + tf.w)));
        float g_ = tanhf(gg.w + tg_.w);
        float o_ = 1.f / (1.f + expf(-(go.w + to.w)));
        cv.w = f_ * cp.w + i_ * g_;  hv.w = o_ * tanhf(cv.w);
    }

    *(float4*)(out + (size_t)b * H_DIM + j) = hv;
    *(float4*)(out + (size_t)(B_SZ + b) * H_DIM + j) = cv;
}

// ---------------- launch ----------------
extern "C" void kernel_launch(void* const* d_in, const int* in_sizes, int n_in,
                              void* d_out, int out_size) {
    const float* x      = (const float*)d_in[0];
    const float* h_prev = (const float*)d_in[1];
    const float* c_prev = (const float*)d_in[2];
    const float* Win    = (const float*)d_in[3];
    const float* A      = (const float*)d_in[4];
    const float* Bm     = (const float*)d_in[5];
    float* out = (float*)d_out;

    void *p_s, *p_t, *p_wh;
    cudaGetSymbolAddress(&p_s, g_s);
    cudaGetSymbolAddress(&p_t, g_t);
    cudaGetSymbolAddress(&p_wh, g_wh);

    cudaFuncSetAttribute(gemm_fused_kernel, cudaFuncAttributeMaxDynamicSharedMemorySize,
                         GSMEM_BYTES);

    // ordered so the ncu capture slot (#4) lands on gemm_fused
    // 1) W -> fp16
    conv_f16_kernel<<<(G4H * IN_DIM / 4) / 256, 256>>>(Win, (__half*)p_wh);
    // 2) x, h -> fp16 (single launch)
    conv_xh_kernel<<<(2 * XH_QUADS) / 256, 256>>>(x, h_prev);
    // 3) C16 = fp16(A - Bm)
    make_C_kernel<<<64, 256>>>(A, Bm);

    // 4) fused gates GEMM (main + struct), fp16 m16n8k16 + ldmatrix, BK=64
    {
        dim3 grid(G4H / BN, B_SZ / BM);
        gemm_fused_kernel<<<grid, 256, GSMEM_BYTES>>>((const __half*)p_wh);
    }

    // 5) block sums (only feeds t / lstm)
    sum_blocks_kernel<<<B_SZ, HB>>>(h_prev);
    // 6) fp32 t = s @ Bm^T
    {
        dim3 grid(512 / 128, B_SZ / 128);
        gemm_nt_kernel<<<grid, 256>>>((const float*)p_s, Bm, (float*)p_t,
                                      HB, HB, HB, 4 * HB);
    }

    // 7) elementwise LSTM cell (+ t-term)
    lstm_elem_kernel<<<(B_SZ * H_DIM / 4) / 256, 256>>>(c_prev, out);
}